// round 13
// baseline (speedup 1.0000x reference)
#include <cuda_runtime.h>
#include <cstdint>

#define BB 16
#define DD 128
#define MM 4096
#define VV 32000
#define BM (BB*MM)

// ---------------- scratch (static device globals; no allocation) ----------------
__device__ __align__(16) float g_u[BB*DD];   // current query u  [B][D]
__device__ __align__(16) float g_t[BB*VV];   // score table t[b][v] = C_h[v].u[b]
__device__ __align__(16) float g_w[BB*VV];   // scattered (unnormalized) exp weights
__device__ float g_sum[BB];                  // softmax denominators
__device__ int g_is64;                       // story dtype flag (1 if int64)

// ---------------- helpers ----------------
__device__ __forceinline__ int4 load_toks(const int* __restrict__ story, int idx) {
    if (!g_is64) {
        return ((const int4*)story)[idx];
    } else {
        longlong4 l = ((const longlong4*)story)[idx];
        return make_int4((int)l.x, (int)l.y, (int)l.z, (int)l.w);
    }
}

// pack2(hi,lo): bf16x2 with .lo = bf16(lo), .hi = bf16(hi)
__device__ __forceinline__ uint32_t pack2(float hi, float lo) {
    uint32_t r;
    asm("cvt.rn.bf16x2.f32 %0, %1, %2;" : "=r"(r) : "f"(hi), "f"(lo));
    return r;
}
__device__ __forceinline__ float lo_f(uint32_t p) { return __uint_as_float(p << 16); }
__device__ __forceinline__ float hi_f(uint32_t p) { return __uint_as_float(p & 0xffff0000u); }

#define LDSM4(r0,r1,r2,r3,addr) \
  asm volatile("ldmatrix.sync.aligned.m8n8.x4.shared.b16 {%0,%1,%2,%3}, [%4];" \
               : "=r"(r0),"=r"(r1),"=r"(r2),"=r"(r3) : "r"(addr))

#define MMA16816(d0,d1,d2,d3,a0,a1,a2,a3,b0,b1) \
  asm volatile("mma.sync.aligned.m16n8k16.row.col.f32.bf16.bf16.f32 " \
               "{%0,%1,%2,%3}, {%4,%5,%6,%7}, {%8,%9}, {%0,%1,%2,%3};" \
               : "+f"(d0),"+f"(d1),"+f"(d2),"+f"(d3) \
               : "r"(a0),"r"(a1),"r"(a2),"r"(a3),"r"(b0),"r"(b1))

// ---------------- kernels ----------------

// t[b][v] = dot(C_h[v], u[b]) via split-bf16 tensor-core MMA.
// Grid MUST be 1000 x 128. One 32-row tile per block, NO fp32 smem staging:
// each thread streams its 8 contiguous float4 (one 128B line per lane) via
// LDG (front-batched, MLP=8), converts in registers, writes bf16 hi/lo
// directly to padded smem. Removes a full smem round-trip and keeps DRAM
// load issue continuous across the ~6 resident blocks/SM.
// Warp roles: tile16 = warp>>1 (rows 16*tile16..+16), ngrp = warp&1 (b 8*ngrp..+8).
// 8 ksteps x (2 ldmatrix.x4 + 3 mma): D += Ch*uh + Cl*uh + Ch*ul (resid ~5e-6)
template <bool FIRST, bool ZERO_W, bool COPY_U, bool USE_GU>
__global__ void __launch_bounds__(128) k_dot(const float* __restrict__ Cg,
                                             const float* __restrict__ uin,
                                             float* __restrict__ u_out,
                                             const int* __restrict__ story) {
    __shared__ __align__(16) uint16_t CHs[32*136];    // bf16 hi, 8.5KB
    __shared__ __align__(16) uint16_t CLs[32*136];    // bf16 lo, 8.5KB
    __shared__ __align__(16) float TS[16*36];         // D staging, 2.3KB

    const int tid  = threadIdx.x;
    const int warp = tid >> 5;
    const int lane = tid & 31;

    if (ZERO_W) {
        int j = blockIdx.x*128 + tid;                 // 128000 threads == BB*VV/4
        if (j < BB*VV/4) ((float4*)g_w)[j] = make_float4(0.f, 0.f, 0.f, 0.f);
        if (blockIdx.x == 0 && tid < BB) g_sum[tid] = 0.f;
    }
    if (FIRST && blockIdx.x == 0) {
        for (int j = tid; j < BB*DD; j += 128) g_u[j] = uin[j];
        if (tid == 0) {
            // int64 little-endian: odd words are high words of small tokens -> 0
            int z = story[1] | story[3] | story[5] | story[7];
            g_is64 = (z == 0) ? 1 : 0;
        }
    }
    if (COPY_U && blockIdx.x == 0) {
        for (int j = tid; j < BB*DD; j += 128) u_out[j] = g_u[j];
    }

    const int v0 = blockIdx.x * 32;

    // ---- stream C rows through registers -> bf16 hi/lo smem.
    // thread (row = tid>>2, q = tid&3) owns the 128B line [q*32, q*32+32) floats.
    {
        const int row = tid >> 2;
        const int q   = tid & 3;
        const float4* src = (const float4*)(Cg + (size_t)(v0 + row) * DD) + q*8;

        float4 v[8];
        #pragma unroll
        for (int k = 0; k < 8; k++) v[k] = src[k];    // 8 front-batched LDG.128

        #pragma unroll
        for (int k = 0; k < 8; k++) {
            float4 f = v[k];
            uint32_t h01 = pack2(f.y, f.x);
            uint32_t h23 = pack2(f.w, f.z);
            uint32_t l01 = pack2(f.y - hi_f(h01), f.x - lo_f(h01));
            uint32_t l23 = pack2(f.w - hi_f(h23), f.z - lo_f(h23));
            *(uint2*)(CHs + row*136 + (q*8 + k)*4) = make_uint2(h01, h23);
            *(uint2*)(CLs + row*136 + (q*8 + k)*4) = make_uint2(l01, l23);
        }
    }

    // ---- B fragments (u split hi/lo)
    const int ngrp   = warp & 1;
    const int tile16 = warp >> 1;
    const int bidx   = ngrp*8 + (lane >> 2);

    uint32_t Bh0[8], Bh1[8], Bl0[8], Bl1[8];
    {
        const float* usrc = USE_GU ? g_u : uin;
        const float2* u2 = (const float2*)(usrc + bidx*DD);
        #pragma unroll
        for (int k = 0; k < 8; k++) {
            float2 p = u2[8*k + (lane&3)];
            float2 r = u2[8*k + 4 + (lane&3)];
            uint32_t hp = pack2(p.y, p.x);
            Bh0[k] = hp;
            Bl0[k] = pack2(p.y - hi_f(hp), p.x - lo_f(hp));
            uint32_t hr = pack2(r.y, r.x);
            Bh1[k] = hr;
            Bl1[k] = pack2(r.y - hi_f(hr), r.x - lo_f(hr));
        }
    }

    const uint32_t aoff = (uint32_t)((tile16*16 + (lane & 15))*272 + ((lane >> 4)*8)*2);
    const uint32_t ch_base = (uint32_t)__cvta_generic_to_shared(CHs) + aoff;
    const uint32_t cl_base = (uint32_t)__cvta_generic_to_shared(CLs) + aoff;

    __syncthreads();

    // ---- MMA: 8 ksteps x 3 combos
    float d0 = 0.f, d1 = 0.f, d2 = 0.f, d3 = 0.f;
    #pragma unroll
    for (int k = 0; k < 8; k++) {
        uint32_t ah0, ah1, ah2, ah3, al0, al1, al2, al3;
        LDSM4(ah0, ah1, ah2, ah3, ch_base + k*32);
        LDSM4(al0, al1, al2, al3, cl_base + k*32);
        MMA16816(d0, d1, d2, d3, ah0, ah1, ah2, ah3, Bh0[k], Bh1[k]);
        MMA16816(d0, d1, d2, d3, al0, al1, al2, al3, Bh0[k], Bh1[k]);
        MMA16816(d0, d1, d2, d3, ah0, ah1, ah2, ah3, Bl0[k], Bl1[k]);
    }

    // ---- stage D to TS[b][v_local] (padded [16][36])
    {
        int row0 = lane >> 2, colb = (lane & 3)*2;
        int vloc = tile16*16 + row0;
        TS[(ngrp*8 + colb    )*36 + vloc    ] = d0;
        TS[(ngrp*8 + colb + 1)*36 + vloc    ] = d1;
        TS[(ngrp*8 + colb    )*36 + vloc + 8] = d2;
        TS[(ngrp*8 + colb + 1)*36 + vloc + 8] = d3;
    }
    __syncthreads();

    // ---- coalesced store: thread (b = tid>>3, chunk = tid&7) -> STG.128
    {
        int b = tid >> 3, chn = tid & 7;
        float4 val = *(float4*)&TS[b*36 + chn*4];
        *(float4*)(g_t + b*VV + v0 + chn*4) = val;
    }
}

// Fused attention: logits -> exp (no max shift; logits are O(10) by construction)
// -> scatter unnormalized e into g_w, accumulate per-b sum via one block atomic.
__global__ void __launch_bounds__(256) k_att(const int* __restrict__ story) {
    const int i = blockIdx.x*256 + threadIdx.x;
    const int b = i >> 12;
    int4 tk = load_toks(story, i);
    const float* tb = g_t + b*VV;
    float val = tb[tk.x] + tb[tk.y] + tb[tk.z] + tb[tk.w];
    float e = __expf(val);

    float s = e;
    #pragma unroll
    for (int o = 16; o; o >>= 1) s += __shfl_xor_sync(0xffffffffu, s, o);
    __shared__ float sw[8];
    const int lane = threadIdx.x & 31, wid = threadIdx.x >> 5;
    if (lane == 0) sw[wid] = s;
    __syncthreads();
    if (threadIdx.x == 0) {
        float t = 0.f;
        #pragma unroll
        for (int k = 0; k < 8; k++) t += sw[k];
        atomicAdd(&g_sum[b], t);
    }

    float* wb = g_w + b*VV;
    atomicAdd(&wb[tk.x], e);
    atomicAdd(&wb[tk.y], e);
    atomicAdd(&wb[tk.z], e);
    atomicAdd(&wb[tk.w], e);
}

// u[b][d] += sum_v (w[b][v]/sum[b]) * C_next[v][d]
// 500 blocks x 256 threads; block covers UVC=64 vocab rows for all 16 b.
// C tile staged into smem via cp.async; w prescale overlaps the stream.
#define UVC 64
__global__ void __launch_bounds__(256) k_update(const float* __restrict__ Cn) {
    __shared__ __align__(16) float Csm[UVC][DD];      // 32KB
    __shared__ __align__(16) float wsh[BB][UVC];      // 4KB
    __shared__ float sinv[BB];
    const int tid = threadIdx.x;
    const int d   = tid & 127;
    const int b0  = (tid >> 7) * 8;
    const int v0  = blockIdx.x * UVC;

    {
        uint32_t sb = (uint32_t)__cvta_generic_to_shared(Csm);
        const float4* src = (const float4*)(Cn + (size_t)v0 * DD);
        #pragma unroll
        for (int k = 0; k < 8; k++) {
            int c = tid + k*256;
            asm volatile("cp.async.cg.shared.global [%0], [%1], 16;\n"
                         :: "r"(sb + c*16), "l"(src + c));
        }
        asm volatile("cp.async.commit_group;\n");
    }

    if (tid < BB) sinv[tid] = 1.0f / g_sum[tid];
    __syncthreads();
    #pragma unroll
    for (int j = tid; j < BB*UVC; j += 256) {
        int b = j >> 6, vi = j & (UVC-1);
        wsh[b][vi] = g_w[b*VV + v0 + vi] * sinv[b];
    }
    asm volatile("cp.async.wait_group 0;\n" ::: "memory");
    __syncthreads();

    float acc[8];
    #pragma unroll
    for (int b = 0; b < 8; b++) acc[b] = 0.f;

    #pragma unroll 4
    for (int vi4 = 0; vi4 < UVC/4; vi4++) {
        float c0 = Csm[vi4*4 + 0][d];
        float c1 = Csm[vi4*4 + 1][d];
        float c2 = Csm[vi4*4 + 2][d];
        float c3 = Csm[vi4*4 + 3][d];
        #pragma unroll
        for (int b = 0; b < 8; b++) {
            float4 w = ((const float4*)wsh[b0 + b])[vi4];
            acc[b] += w.x*c0;
            acc[b] += w.y*c1;
            acc[b] += w.z*c2;
            acc[b] += w.w*c3;
        }
    }

    #pragma unroll
    for (int b = 0; b < 8; b++)
        atomicAdd(&g_u[(b0 + b)*DD + d], acc[b]);
}

// final-hop logits straight to output
__global__ void __launch_bounds__(256) k_logits_out(const int* __restrict__ story,
                                                    float* __restrict__ out) {
    const int i = blockIdx.x*256 + threadIdx.x;
    const int b = i >> 12;
    int4 tk = load_toks(story, i);
    const float* tb = g_t + b*VV;
    out[i] = tb[tk.x] + tb[tk.y] + tb[tk.z] + tb[tk.w];
}

// ---------------- launch ----------------
extern "C" void kernel_launch(void* const* d_in, const int* in_sizes, int n_in,
                              void* d_out, int out_size) {
    const int*   story = (const int*)d_in[0];
    const float* q     = (const float*)d_in[1];
    const float* C     = (const float*)d_in[2];
    float* out = (float*)d_out;     // [prob_lg: B*M][u1: B*D]

    const float* C0 = C;
    const float* C1 = C + (size_t)VV * DD;
    const float* C2 = C + 2 * (size_t)VV * DD;

    // ---- hop 0 (u = q read directly; also inits g_u, dtype flag, zeros w) ----
    k_dot<true,  true,  false, false><<<1000, 128>>>(C0, q, nullptr, story);
    k_att<<<BM/256, 256>>>(story);
    k_update<<<VV/UVC, 256>>>(C1);

    // ---- hop 1 (dot also emits u1 = g_u to out) ----
    k_dot<false, true,  true,  true ><<<1000, 128>>>(C1, nullptr, out + BM, story);
    k_att<<<BM/256, 256>>>(story);
    k_update<<<VV/UVC, 256>>>(C2);

    // ---- hop 2: only logits needed (they ARE prob_lg) ----
    k_dot<false, false, false, true ><<<1000, 128>>>(C2, nullptr, nullptr, story);
    k_logits_out<<<BM/256, 256>>>(story, out);
}

// round 14
// speedup vs baseline: 1.2310x; 1.2310x over previous
#include <cuda_runtime.h>
#include <cstdint>

#define BB 16
#define DD 128
#define MM 4096
#define VV 32000
#define BM (BB*MM)

// ---------------- scratch (static device globals; no allocation) ----------------
__device__ __align__(16) float g_u[BB*DD];   // current query u  [B][D]
__device__ __align__(16) float g_t[BB*VV];   // score table t[b][v] = C_h[v].u[b]
__device__ __align__(16) float g_w[BB*VV];   // scattered (unnormalized) exp weights
__device__ float g_sum[BB];                  // softmax denominators
__device__ int g_is64;                       // story dtype flag (1 if int64)

// ---------------- helpers ----------------
__device__ __forceinline__ int4 load_toks(const int* __restrict__ story, int idx) {
    if (!g_is64) {
        return ((const int4*)story)[idx];
    } else {
        longlong4 l = ((const longlong4*)story)[idx];
        return make_int4((int)l.x, (int)l.y, (int)l.z, (int)l.w);
    }
}

// pack2(hi,lo): bf16x2 with .lo = bf16(lo), .hi = bf16(hi)
__device__ __forceinline__ uint32_t pack2(float hi, float lo) {
    uint32_t r;
    asm("cvt.rn.bf16x2.f32 %0, %1, %2;" : "=r"(r) : "f"(hi), "f"(lo));
    return r;
}
__device__ __forceinline__ float lo_f(uint32_t p) { return __uint_as_float(p << 16); }
__device__ __forceinline__ float hi_f(uint32_t p) { return __uint_as_float(p & 0xffff0000u); }

#define LDSM4(r0,r1,r2,r3,addr) \
  asm volatile("ldmatrix.sync.aligned.m8n8.x4.shared.b16 {%0,%1,%2,%3}, [%4];" \
               : "=r"(r0),"=r"(r1),"=r"(r2),"=r"(r3) : "r"(addr))

#define MMA16816(d0,d1,d2,d3,a0,a1,a2,a3,b0,b1) \
  asm volatile("mma.sync.aligned.m16n8k16.row.col.f32.bf16.bf16.f32 " \
               "{%0,%1,%2,%3}, {%4,%5,%6,%7}, {%8,%9}, {%0,%1,%2,%3};" \
               : "+f"(d0),"+f"(d1),"+f"(d2),"+f"(d3) \
               : "r"(a0),"r"(a1),"r"(a2),"r"(a3),"r"(b0),"r"(b1))

// smem: SF0 fp32 tile (16KB) | SF1 fp32 tile (16KB) | CHs bf16 (8.5KB) | CLs (8.5KB)
// TS (16x36 f32, 2.3KB) aliases SF0 (dead after its tile's conversion).
#define SMEM_BYTES (32768 + 8704 + 8704)

// ---------------- kernels ----------------

// t[b][v] = dot(C_h[v], u[b]) via split-bf16 tensor-core MMA.  (R11 version:
// best measured k_dot, 10.2us.)  Grid MUST be 500 x 128. Block covers 64 rows
// = 2 tiles of 32 rows, double-buffered cp.async fp32 staging.
// Warp roles: tile16 = warp>>1 (rows 16*tile16..+16), ngrp = warp&1 (b 8*ngrp..+8).
// Per tile: fp32 -> bf16 hi/lo split in smem (padded 136-col rows), 8 ksteps x
// (2 ldmatrix.x4 + 3 mma):  D += Ch*uh + Cl*uh + Ch*ul  (residual ~5e-6)
template <bool FIRST, bool ZERO_W, bool COPY_U, bool USE_GU>
__global__ void __launch_bounds__(128) k_dot(const float* __restrict__ Cg,
                                             const float* __restrict__ uin,
                                             float* __restrict__ u_out,
                                             const int* __restrict__ story) {
    extern __shared__ __align__(16) char smem_raw[];
    float4*   SF0 = (float4*)smem_raw;                 // [32][32] float4
    float4*   SF1 = SF0 + 32*32;
    uint16_t* CHs = (uint16_t*)(SF1 + 32*32);          // [32][136] bf16
    uint16_t* CLs = CHs + 32*136;
    float*    TS  = (float*)smem_raw;                  // [16][36] (aliases SF0)

    const int tid  = threadIdx.x;
    const int warp = tid >> 5;
    const int lane = tid & 31;

    if (ZERO_W) {
        const int nt = gridDim.x * 128;                // 64000 threads, 2 iters
        for (int j = blockIdx.x*128 + tid; j < BB*VV/4; j += nt)
            ((float4*)g_w)[j] = make_float4(0.f, 0.f, 0.f, 0.f);
        if (blockIdx.x == 0 && tid < BB) g_sum[tid] = 0.f;
    }
    if (FIRST && blockIdx.x == 0) {
        for (int j = tid; j < BB*DD; j += 128) g_u[j] = uin[j];
        if (tid == 0) {
            // int64 little-endian: odd words are high words of small tokens -> 0
            int z = story[1] | story[3] | story[5] | story[7];
            g_is64 = (z == 0) ? 1 : 0;
        }
    }
    if (COPY_U && blockIdx.x == 0) {
        for (int j = tid; j < BB*DD; j += 128) u_out[j] = g_u[j];
    }

    const int v0 = blockIdx.x * 64;

    auto load_tile = [&](float4* SF, int tt) {
        uint32_t sb = (uint32_t)__cvta_generic_to_shared(SF);
        const float4* src = (const float4*)(Cg + (size_t)(v0 + tt*32) * DD);
        #pragma unroll
        for (int k = 0; k < 8; k++) {
            int c = tid + k*128;
            asm volatile("cp.async.cg.shared.global [%0], [%1], 16;\n"
                         :: "r"(sb + c*16), "l"(src + c));
        }
        asm volatile("cp.async.commit_group;\n");
    };

    load_tile(SF0, 0);

    // ---- B fragments (u split hi/lo), built while tile 0 streams in
    const int ngrp   = warp & 1;
    const int tile16 = warp >> 1;
    const int bidx   = ngrp*8 + (lane >> 2);

    uint32_t Bh0[8], Bh1[8], Bl0[8], Bl1[8];
    {
        const float* usrc = USE_GU ? g_u : uin;
        const float2* u2 = (const float2*)(usrc + bidx*DD);
        #pragma unroll
        for (int k = 0; k < 8; k++) {
            float2 p = u2[8*k + (lane&3)];
            float2 r = u2[8*k + 4 + (lane&3)];
            uint32_t hp = pack2(p.y, p.x);
            Bh0[k] = hp;
            Bl0[k] = pack2(p.y - hi_f(hp), p.x - lo_f(hp));
            uint32_t hr = pack2(r.y, r.x);
            Bh1[k] = hr;
            Bl1[k] = pack2(r.y - hi_f(hr), r.x - lo_f(hr));
        }
    }

    load_tile(SF1, 1);

    // ldmatrix lane address: row = lane&15 of this warp's 16-row tile,
    // col chunk = (lane>>4)*8 bf16 ; row stride 272B (136 bf16, conflict-free)
    const uint32_t aoff = (uint32_t)((tile16*16 + (lane & 15))*272 + ((lane >> 4)*8)*2);
    const uint32_t ch_base = (uint32_t)__cvta_generic_to_shared(CHs) + aoff;
    const uint32_t cl_base = (uint32_t)__cvta_generic_to_shared(CLs) + aoff;

    #pragma unroll
    for (int t = 0; t < 2; t++) {
        if (t == 0) asm volatile("cp.async.wait_group 1;\n" ::: "memory");
        else        asm volatile("cp.async.wait_group 0;\n" ::: "memory");
        __syncthreads();

        // ---- fp32 -> bf16 hi/lo split into padded smem (8 float4 per thread)
        const float4* SF = t ? SF1 : SF0;
        #pragma unroll
        for (int k = 0; k < 8; k++) {
            int c = tid + k*128;
            int row = c >> 5, col = c & 31;
            float4 f = SF[c];
            uint32_t h01 = pack2(f.y, f.x);
            uint32_t h23 = pack2(f.w, f.z);
            uint32_t l01 = pack2(f.y - hi_f(h01), f.x - lo_f(h01));
            uint32_t l23 = pack2(f.w - hi_f(h23), f.z - lo_f(h23));
            *(uint2*)(CHs + row*136 + col*4) = make_uint2(h01, h23);
            *(uint2*)(CLs + row*136 + col*4) = make_uint2(l01, l23);
        }
        __syncthreads();

        // ---- MMA: 8 ksteps x 3 combos
        float d0 = 0.f, d1 = 0.f, d2 = 0.f, d3 = 0.f;
        #pragma unroll
        for (int k = 0; k < 8; k++) {
            uint32_t ah0, ah1, ah2, ah3, al0, al1, al2, al3;
            LDSM4(ah0, ah1, ah2, ah3, ch_base + k*32);
            LDSM4(al0, al1, al2, al3, cl_base + k*32);
            MMA16816(d0, d1, d2, d3, ah0, ah1, ah2, ah3, Bh0[k], Bh1[k]);
            MMA16816(d0, d1, d2, d3, al0, al1, al2, al3, Bh0[k], Bh1[k]);
            MMA16816(d0, d1, d2, d3, ah0, ah1, ah2, ah3, Bl0[k], Bl1[k]);
        }

        // ---- stage D to TS[b][v_local] (padded [16][36], conflict-free)
        {
            int row0 = lane >> 2, colb = (lane & 3)*2;
            int vloc = tile16*16 + row0;
            TS[(ngrp*8 + colb    )*36 + vloc    ] = d0;
            TS[(ngrp*8 + colb + 1)*36 + vloc    ] = d1;
            TS[(ngrp*8 + colb    )*36 + vloc + 8] = d2;
            TS[(ngrp*8 + colb + 1)*36 + vloc + 8] = d3;
        }
        __syncthreads();

        // ---- coalesced store: thread (b = tid>>3, chunk = tid&7) -> STG.128
        {
            int b = tid >> 3, chn = tid & 7;
            float4 val = *(float4*)&TS[b*36 + chn*4];
            *(float4*)(g_t + b*VV + v0 + t*32 + chn*4) = val;
        }
    }
}

// Fused attention: logits -> exp (no max shift; logits are O(10) by construction)
// -> scatter unnormalized e into g_w, accumulate per-b sum via one block atomic.
__global__ void __launch_bounds__(256) k_att(const int* __restrict__ story) {
    const int i = blockIdx.x*256 + threadIdx.x;
    const int b = i >> 12;
    int4 tk = load_toks(story, i);
    const float* tb = g_t + b*VV;
    float val = tb[tk.x] + tb[tk.y] + tb[tk.z] + tb[tk.w];
    float e = __expf(val);

    float s = e;
    #pragma unroll
    for (int o = 16; o; o >>= 1) s += __shfl_xor_sync(0xffffffffu, s, o);
    __shared__ float sw[8];
    const int lane = threadIdx.x & 31, wid = threadIdx.x >> 5;
    if (lane == 0) sw[wid] = s;
    __syncthreads();
    if (threadIdx.x == 0) {
        float t = 0.f;
        #pragma unroll
        for (int k = 0; k < 8; k++) t += sw[k];
        atomicAdd(&g_sum[b], t);
    }

    float* wb = g_w + b*VV;
    atomicAdd(&wb[tk.x], e);
    atomicAdd(&wb[tk.y], e);
    atomicAdd(&wb[tk.z], e);
    atomicAdd(&wb[tk.w], e);
}

// u[b][d] += sum_v (w[b][v]/sum[b]) * C_next[v][d]   (R12 version: cp.async
// staged C tile; inner loop from smem.)
// 500 blocks x 256 threads; block covers UVC=64 vocab rows for all 16 b.
#define UVC 64
__global__ void __launch_bounds__(256) k_update(const float* __restrict__ Cn) {
    __shared__ __align__(16) float Csm[UVC][DD];      // 32KB
    __shared__ __align__(16) float wsh[BB][UVC];      // 4KB
    __shared__ float sinv[BB];
    const int tid = threadIdx.x;
    const int d   = tid & 127;
    const int b0  = (tid >> 7) * 8;
    const int v0  = blockIdx.x * UVC;

    {
        uint32_t sb = (uint32_t)__cvta_generic_to_shared(Csm);
        const float4* src = (const float4*)(Cn + (size_t)v0 * DD);
        #pragma unroll
        for (int k = 0; k < 8; k++) {
            int c = tid + k*256;
            asm volatile("cp.async.cg.shared.global [%0], [%1], 16;\n"
                         :: "r"(sb + c*16), "l"(src + c));
        }
        asm volatile("cp.async.commit_group;\n");
    }

    if (tid < BB) sinv[tid] = 1.0f / g_sum[tid];
    __syncthreads();
    #pragma unroll
    for (int j = tid; j < BB*UVC; j += 256) {
        int b = j >> 6, vi = j & (UVC-1);
        wsh[b][vi] = g_w[b*VV + v0 + vi] * sinv[b];
    }
    asm volatile("cp.async.wait_group 0;\n" ::: "memory");
    __syncthreads();

    float acc[8];
    #pragma unroll
    for (int b = 0; b < 8; b++) acc[b] = 0.f;

    #pragma unroll 4
    for (int vi4 = 0; vi4 < UVC/4; vi4++) {
        float c0 = Csm[vi4*4 + 0][d];                 // conflict-free: bank = d%32
        float c1 = Csm[vi4*4 + 1][d];
        float c2 = Csm[vi4*4 + 2][d];
        float c3 = Csm[vi4*4 + 3][d];
        #pragma unroll
        for (int b = 0; b < 8; b++) {
            float4 w = ((const float4*)wsh[b0 + b])[vi4];   // broadcast LDS.128
            acc[b] += w.x*c0;
            acc[b] += w.y*c1;
            acc[b] += w.z*c2;
            acc[b] += w.w*c3;
        }
    }

    #pragma unroll
    for (int b = 0; b < 8; b++)
        atomicAdd(&g_u[(b0 + b)*DD + d], acc[b]);
}

// final-hop logits straight to output
__global__ void __launch_bounds__(256) k_logits_out(const int* __restrict__ story,
                                                    float* __restrict__ out) {
    const int i = blockIdx.x*256 + threadIdx.x;
    const int b = i >> 12;
    int4 tk = load_toks(story, i);
    const float* tb = g_t + b*VV;
    out[i] = tb[tk.x] + tb[tk.y] + tb[tk.z] + tb[tk.w];
}

// ---------------- launch ----------------
extern "C" void kernel_launch(void* const* d_in, const int* in_sizes, int n_in,
                              void* d_out, int out_size) {
    const int*   story = (const int*)d_in[0];
    const float* q     = (const float*)d_in[1];
    const float* C     = (const float*)d_in[2];
    float* out = (float*)d_out;     // [prob_lg: B*M][u1: B*D]

    const float* C0 = C;
    const float* C1 = C + (size_t)VV * DD;
    const float* C2 = C + 2 * (size_t)VV * DD;

    // raise dynamic smem cap (idempotent; no allocation)
    cudaFuncSetAttribute(k_dot<true,  true,  false, false>,
                         cudaFuncAttributeMaxDynamicSharedMemorySize, SMEM_BYTES);
    cudaFuncSetAttribute(k_dot<false, true,  true,  true >,
                         cudaFuncAttributeMaxDynamicSharedMemorySize, SMEM_BYTES);
    cudaFuncSetAttribute(k_dot<false, false, false, true >,
                         cudaFuncAttributeMaxDynamicSharedMemorySize, SMEM_BYTES);

    // ---- hop 0 (u = q read directly; also inits g_u, dtype flag, zeros w) ----
    k_dot<true,  true,  false, false><<<500, 128, SMEM_BYTES>>>(C0, q, nullptr, story);
    k_att<<<BM/256, 256>>>(story);
    k_update<<<VV/UVC, 256>>>(C1);

    // ---- hop 1 (dot also emits u1 = g_u to out) ----
    k_dot<false, true,  true,  true ><<<500, 128, SMEM_BYTES>>>(C1, nullptr, out + BM, story);
    k_att<<<BM/256, 256>>>(story);
    k_update<<<VV/UVC, 256>>>(C2);

    // ---- hop 2: only logits needed (they ARE prob_lg) ----
    k_dot<false, false, false, true ><<<500, 128, SMEM_BYTES>>>(C2, nullptr, nullptr, story);
    k_logits_out<<<BM/256, 256>>>(story, out);
}

// round 15
// speedup vs baseline: 1.2317x; 1.0006x over previous
#include <cuda_runtime.h>
#include <cstdint>

#define BB 16
#define DD 128
#define MM 4096
#define VV 32000
#define BM (BB*MM)

// ---------------- scratch (static device globals; no allocation) ----------------
__device__ __align__(16) float g_u[BB*DD];   // current query u  [B][D]
__device__ __align__(16) float g_t[BB*VV];   // score table t[b][v] = C_h[v].u[b]
__device__ __align__(16) float g_w[BB*VV];   // scattered (unnormalized) exp weights
__device__ float g_sum[BB];                  // softmax denominators
__device__ int g_is64;                       // story dtype flag (1 if int64)

// ---------------- helpers ----------------
__device__ __forceinline__ int4 load_toks(const int* __restrict__ story, int idx) {
    if (!g_is64) {
        return ((const int4*)story)[idx];
    } else {
        longlong4 l = ((const longlong4*)story)[idx];
        return make_int4((int)l.x, (int)l.y, (int)l.z, (int)l.w);
    }
}

// pack2(hi,lo): bf16x2 with .lo = bf16(lo), .hi = bf16(hi)
__device__ __forceinline__ uint32_t pack2(float hi, float lo) {
    uint32_t r;
    asm("cvt.rn.bf16x2.f32 %0, %1, %2;" : "=r"(r) : "f"(hi), "f"(lo));
    return r;
}
__device__ __forceinline__ float lo_f(uint32_t p) { return __uint_as_float(p << 16); }
__device__ __forceinline__ float hi_f(uint32_t p) { return __uint_as_float(p & 0xffff0000u); }

#define LDSM4(r0,r1,r2,r3,addr) \
  asm volatile("ldmatrix.sync.aligned.m8n8.x4.shared.b16 {%0,%1,%2,%3}, [%4];" \
               : "=r"(r0),"=r"(r1),"=r"(r2),"=r"(r3) : "r"(addr))

#define MMA16816(d0,d1,d2,d3,a0,a1,a2,a3,b0,b1) \
  asm volatile("mma.sync.aligned.m16n8k16.row.col.f32.bf16.bf16.f32 " \
               "{%0,%1,%2,%3}, {%4,%5,%6,%7}, {%8,%9}, {%0,%1,%2,%3};" \
               : "+f"(d0),"+f"(d1),"+f"(d2),"+f"(d3) \
               : "r"(a0),"r"(a1),"r"(a2),"r"(a3),"r"(b0),"r"(b1))

// smem: SF0|SF1 fp32 tiles (32KB) | CHs bf16 (8.5KB) | CLs (8.5KB) | TS (2.3KB)
#define SMEM_BYTES (32768 + 8704 + 8704 + 2304)

// ---------------- kernels ----------------

#define TILES 4

// t[b][v] = dot(C_h[v], u[b]) via split-bf16 tensor-core MMA.
// Grid MUST be 250 x 128. Block covers 128 rows = 4 tiles of 32 rows on a
// 2-buffer cp.async ring: convert tile t frees SF[t&1], which immediately
// reloads tile t+2 -> 2 tile-loads in flight for most of the block's life
// (R14 had TILES=2: zero DRAM traffic after the prologue).
// Warp roles: tile16 = warp>>1 (rows 16*tile16..+16), ngrp = warp&1 (b 8*ngrp..+8).
// Per tile: fp32 -> bf16 hi/lo split smem (padded 136-col rows), 8 ksteps x
// (2 ldmatrix.x4 + 3 mma):  D += Ch*uh + Cl*uh + Ch*ul  (residual ~5e-6)
template <bool FIRST, bool ZERO_W, bool COPY_U, bool USE_GU>
__global__ void __launch_bounds__(128) k_dot(const float* __restrict__ Cg,
                                             const float* __restrict__ uin,
                                             float* __restrict__ u_out,
                                             const int* __restrict__ story) {
    extern __shared__ __align__(16) char smem_raw[];
    float4*   SF0 = (float4*)smem_raw;                 // [32][32] float4
    float4*   SF1 = SF0 + 32*32;
    uint16_t* CHs = (uint16_t*)(SF1 + 32*32);          // [32][136] bf16
    uint16_t* CLs = CHs + 32*136;
    float*    TS  = (float*)(CLs + 32*136);            // [16][36]

    const int tid  = threadIdx.x;
    const int warp = tid >> 5;
    const int lane = tid & 31;

    if (ZERO_W) {
        const int nt = gridDim.x * 128;                // 32000 threads, 4 iters
        for (int j = blockIdx.x*128 + tid; j < BB*VV/4; j += nt)
            ((float4*)g_w)[j] = make_float4(0.f, 0.f, 0.f, 0.f);
        if (blockIdx.x == 0 && tid < BB) g_sum[tid] = 0.f;
    }
    if (FIRST && blockIdx.x == 0) {
        for (int j = tid; j < BB*DD; j += 128) g_u[j] = uin[j];
        if (tid == 0) {
            // int64 little-endian: odd words are high words of small tokens -> 0
            int z = story[1] | story[3] | story[5] | story[7];
            g_is64 = (z == 0) ? 1 : 0;
        }
    }
    if (COPY_U && blockIdx.x == 0) {
        for (int j = tid; j < BB*DD; j += 128) u_out[j] = g_u[j];
    }

    const int v0 = blockIdx.x * (TILES*32);

    auto load_tile = [&](float4* SF, int tt) {
        uint32_t sb = (uint32_t)__cvta_generic_to_shared(SF);
        const float4* src = (const float4*)(Cg + (size_t)(v0 + tt*32) * DD);
        #pragma unroll
        for (int k = 0; k < 8; k++) {
            int c = tid + k*128;
            asm volatile("cp.async.cg.shared.global [%0], [%1], 16;\n"
                         :: "r"(sb + c*16), "l"(src + c));
        }
        asm volatile("cp.async.commit_group;\n");
    };

    load_tile(SF0, 0);

    // ---- B fragments (u split hi/lo), built while tile 0 streams in
    const int ngrp   = warp & 1;
    const int tile16 = warp >> 1;
    const int bidx   = ngrp*8 + (lane >> 2);

    uint32_t Bh0[8], Bh1[8], Bl0[8], Bl1[8];
    {
        const float* usrc = USE_GU ? g_u : uin;
        const float2* u2 = (const float2*)(usrc + bidx*DD);
        #pragma unroll
        for (int k = 0; k < 8; k++) {
            float2 p = u2[8*k + (lane&3)];
            float2 r = u2[8*k + 4 + (lane&3)];
            uint32_t hp = pack2(p.y, p.x);
            Bh0[k] = hp;
            Bl0[k] = pack2(p.y - hi_f(hp), p.x - lo_f(hp));
            uint32_t hr = pack2(r.y, r.x);
            Bh1[k] = hr;
            Bl1[k] = pack2(r.y - hi_f(hr), r.x - lo_f(hr));
        }
    }

    load_tile(SF1, 1);

    // ldmatrix lane address: row = lane&15 of this warp's 16-row tile,
    // col chunk = (lane>>4)*8 bf16 ; row stride 272B (136 bf16, conflict-free)
    const uint32_t aoff = (uint32_t)((tile16*16 + (lane & 15))*272 + ((lane >> 4)*8)*2);
    const uint32_t ch_base = (uint32_t)__cvta_generic_to_shared(CHs) + aoff;
    const uint32_t cl_base = (uint32_t)__cvta_generic_to_shared(CLs) + aoff;

    #pragma unroll
    for (int t = 0; t < TILES; t++) {
        if (t < TILES - 1) asm volatile("cp.async.wait_group 1;\n" ::: "memory");
        else               asm volatile("cp.async.wait_group 0;\n" ::: "memory");
        __syncthreads();

        // ---- fp32 -> bf16 hi/lo split into padded smem (8 float4 per thread)
        float4* SF = (t & 1) ? SF1 : SF0;
        #pragma unroll
        for (int k = 0; k < 8; k++) {
            int c = tid + k*128;
            int row = c >> 5, col = c & 31;
            float4 f = SF[c];
            uint32_t h01 = pack2(f.y, f.x);
            uint32_t h23 = pack2(f.w, f.z);
            uint32_t l01 = pack2(f.y - hi_f(h01), f.x - lo_f(h01));
            uint32_t l23 = pack2(f.w - hi_f(h23), f.z - lo_f(h23));
            *(uint2*)(CHs + row*136 + col*4) = make_uint2(h01, h23);
            *(uint2*)(CLs + row*136 + col*4) = make_uint2(l01, l23);
        }
        __syncthreads();                               // SF now free

        // ---- refill the freed buffer with tile t+2
        if (t + 2 < TILES) load_tile(SF, t + 2);

        // ---- MMA: 8 ksteps x 3 combos
        float d0 = 0.f, d1 = 0.f, d2 = 0.f, d3 = 0.f;
        #pragma unroll
        for (int k = 0; k < 8; k++) {
            uint32_t ah0, ah1, ah2, ah3, al0, al1, al2, al3;
            LDSM4(ah0, ah1, ah2, ah3, ch_base + k*32);
            LDSM4(al0, al1, al2, al3, cl_base + k*32);
            MMA16816(d0, d1, d2, d3, ah0, ah1, ah2, ah3, Bh0[k], Bh1[k]);
            MMA16816(d0, d1, d2, d3, al0, al1, al2, al3, Bh0[k], Bh1[k]);
            MMA16816(d0, d1, d2, d3, ah0, ah1, ah2, ah3, Bl0[k], Bl1[k]);
        }

        // ---- stage D to TS[b][v_local] (padded [16][36], conflict-free)
        {
            int row0 = lane >> 2, colb = (lane & 3)*2;
            int vloc = tile16*16 + row0;
            TS[(ngrp*8 + colb    )*36 + vloc    ] = d0;
            TS[(ngrp*8 + colb + 1)*36 + vloc    ] = d1;
            TS[(ngrp*8 + colb    )*36 + vloc + 8] = d2;
            TS[(ngrp*8 + colb + 1)*36 + vloc + 8] = d3;
        }
        __syncthreads();

        // ---- coalesced store: thread (b = tid>>3, chunk = tid&7) -> STG.128
        {
            int b = tid >> 3, chn = tid & 7;
            float4 val = *(float4*)&TS[b*36 + chn*4];
            *(float4*)(g_t + b*VV + v0 + t*32 + chn*4) = val;
        }
        // loop-top __syncthreads protects TS reuse next tile
    }
}

// Fused attention: logits -> exp (no max shift; logits are O(10) by construction)
// -> scatter unnormalized e into g_w, accumulate per-b sum via one block atomic.
__global__ void __launch_bounds__(256) k_att(const int* __restrict__ story) {
    const int i = blockIdx.x*256 + threadIdx.x;
    const int b = i >> 12;
    int4 tk = load_toks(story, i);
    const float* tb = g_t + b*VV;
    float val = tb[tk.x] + tb[tk.y] + tb[tk.z] + tb[tk.w];
    float e = __expf(val);

    float s = e;
    #pragma unroll
    for (int o = 16; o; o >>= 1) s += __shfl_xor_sync(0xffffffffu, s, o);
    __shared__ float sw[8];
    const int lane = threadIdx.x & 31, wid = threadIdx.x >> 5;
    if (lane == 0) sw[wid] = s;
    __syncthreads();
    if (threadIdx.x == 0) {
        float t = 0.f;
        #pragma unroll
        for (int k = 0; k < 8; k++) t += sw[k];
        atomicAdd(&g_sum[b], t);
    }

    float* wb = g_w + b*VV;
    atomicAdd(&wb[tk.x], e);
    atomicAdd(&wb[tk.y], e);
    atomicAdd(&wb[tk.z], e);
    atomicAdd(&wb[tk.w], e);
}

// u[b][d] += sum_v (w[b][v]/sum[b]) * C_next[v][d]   (cp.async-staged C tile)
// 500 blocks x 256 threads; block covers UVC=64 vocab rows for all 16 b.
#define UVC 64
__global__ void __launch_bounds__(256) k_update(const float* __restrict__ Cn) {
    __shared__ __align__(16) float Csm[UVC][DD];      // 32KB
    __shared__ __align__(16) float wsh[BB][UVC];      // 4KB
    __shared__ float sinv[BB];
    const int tid = threadIdx.x;
    const int d   = tid & 127;
    const int b0  = (tid >> 7) * 8;
    const int v0  = blockIdx.x * UVC;

    {
        uint32_t sb = (uint32_t)__cvta_generic_to_shared(Csm);
        const float4* src = (const float4*)(Cn + (size_t)v0 * DD);
        #pragma unroll
        for (int k = 0; k < 8; k++) {
            int c = tid + k*256;
            asm volatile("cp.async.cg.shared.global [%0], [%1], 16;\n"
                         :: "r"(sb + c*16), "l"(src + c));
        }
        asm volatile("cp.async.commit_group;\n");
    }

    if (tid < BB) sinv[tid] = 1.0f / g_sum[tid];
    __syncthreads();
    #pragma unroll
    for (int j = tid; j < BB*UVC; j += 256) {
        int b = j >> 6, vi = j & (UVC-1);
        wsh[b][vi] = g_w[b*VV + v0 + vi] * sinv[b];
    }
    asm volatile("cp.async.wait_group 0;\n" ::: "memory");
    __syncthreads();

    float acc[8];
    #pragma unroll
    for (int b = 0; b < 8; b++) acc[b] = 0.f;

    #pragma unroll 4
    for (int vi4 = 0; vi4 < UVC/4; vi4++) {
        float c0 = Csm[vi4*4 + 0][d];                 // conflict-free: bank = d%32
        float c1 = Csm[vi4*4 + 1][d];
        float c2 = Csm[vi4*4 + 2][d];
        float c3 = Csm[vi4*4 + 3][d];
        #pragma unroll
        for (int b = 0; b < 8; b++) {
            float4 w = ((const float4*)wsh[b0 + b])[vi4];   // broadcast LDS.128
            acc[b] += w.x*c0;
            acc[b] += w.y*c1;
            acc[b] += w.z*c2;
            acc[b] += w.w*c3;
        }
    }

    #pragma unroll
    for (int b = 0; b < 8; b++)
        atomicAdd(&g_u[(b0 + b)*DD + d], acc[b]);
}

// final-hop logits straight to output
__global__ void __launch_bounds__(256) k_logits_out(const int* __restrict__ story,
                                                    float* __restrict__ out) {
    const int i = blockIdx.x*256 + threadIdx.x;
    const int b = i >> 12;
    int4 tk = load_toks(story, i);
    const float* tb = g_t + b*VV;
    out[i] = tb[tk.x] + tb[tk.y] + tb[tk.z] + tb[tk.w];
}

// ---------------- launch ----------------
extern "C" void kernel_launch(void* const* d_in, const int* in_sizes, int n_in,
                              void* d_out, int out_size) {
    const int*   story = (const int*)d_in[0];
    const float* q     = (const float*)d_in[1];
    const float* C     = (const float*)d_in[2];
    float* out = (float*)d_out;     // [prob_lg: B*M][u1: B*D]

    const float* C0 = C;
    const float* C1 = C + (size_t)VV * DD;
    const float* C2 = C + 2 * (size_t)VV * DD;

    // raise dynamic smem cap (idempotent; no allocation)
    cudaFuncSetAttribute(k_dot<true,  true,  false, false>,
                         cudaFuncAttributeMaxDynamicSharedMemorySize, SMEM_BYTES);
    cudaFuncSetAttribute(k_dot<false, true,  true,  true >,
                         cudaFuncAttributeMaxDynamicSharedMemorySize, SMEM_BYTES);
    cudaFuncSetAttribute(k_dot<false, false, false, true >,
                         cudaFuncAttributeMaxDynamicSharedMemorySize, SMEM_BYTES);

    // ---- hop 0 (u = q read directly; also inits g_u, dtype flag, zeros w) ----
    k_dot<true,  true,  false, false><<<250, 128, SMEM_BYTES>>>(C0, q, nullptr, story);
    k_att<<<BM/256, 256>>>(story);
    k_update<<<VV/UVC, 256>>>(C1);

    // ---- hop 1 (dot also emits u1 = g_u to out) ----
    k_dot<false, true,  true,  true ><<<250, 128, SMEM_BYTES>>>(C1, nullptr, out + BM, story);
    k_att<<<BM/256, 256>>>(story);
    k_update<<<VV/UVC, 256>>>(C2);

    // ---- hop 2: only logits needed (they ARE prob_lg) ----
    k_dot<false, false, false, true ><<<250, 128, SMEM_BYTES>>>(C2, nullptr, nullptr, story);
    k_logits_out<<<BM/256, 256>>>(story, out);
}